// round 15
// baseline (speedup 1.0000x reference)
#include <cuda_runtime.h>
#include <cstdint>

#define N_NODES 50000
#define MAX_EDGES 800000
#define EMB 128
#define NRBF 20

// Scratch (static device arrays are allowed; runtime alloc is not)
__device__ float g_h[(size_t)N_NODES * EMB];         // silu(s@W1+b1), tf32-rounded
__device__ float g_spass[(size_t)N_NODES * 3 * EMB]; // h@W2+b2
__device__ int   g_hist[N_NODES];                    // histogram -> offsets (cursor)
__device__ int2  g_sorted_sd[MAX_EDGES];             // (src, dst) sorted by dst
__device__ int   g_sorted_idx[MAX_EDGES];            // original edge index

// ---------- f32x2 helpers (edge kernel) ----------
__device__ __forceinline__ unsigned long long fma2(unsigned long long a,
                                                   unsigned long long b,
                                                   unsigned long long c) {
    unsigned long long d;
    asm("fma.rn.f32x2 %0, %1, %2, %3;" : "=l"(d) : "l"(a), "l"(b), "l"(c));
    return d;
}
__device__ __forceinline__ unsigned long long packf(float lo, float hi) {
    unsigned long long r;
    asm("mov.b64 %0, {%1, %2};" : "=l"(r) : "f"(lo), "f"(hi));
    return r;
}
__device__ __forceinline__ float lof(unsigned long long v) {
    return __uint_as_float((unsigned)(v & 0xffffffffull));
}
__device__ __forceinline__ float hif(unsigned long long v) {
    return __uint_as_float((unsigned)(v >> 32));
}

// ---------- mma / cp.async helpers ----------
__device__ __forceinline__ unsigned tf32_of(float f) {
    unsigned r;
    asm("cvt.rna.tf32.f32 %0, %1;" : "=r"(r) : "f"(f));
    return r;
}
__device__ __forceinline__ void mma_tf32(float c[4],
                                         unsigned a0, unsigned a1,
                                         unsigned a2, unsigned a3,
                                         unsigned b0, unsigned b1) {
    asm("mma.sync.aligned.m16n8k8.row.col.f32.tf32.tf32.f32 "
        "{%0,%1,%2,%3}, {%4,%5,%6,%7}, {%8,%9}, {%0,%1,%2,%3};"
        : "+f"(c[0]), "+f"(c[1]), "+f"(c[2]), "+f"(c[3])
        : "r"(a0), "r"(a1), "r"(a2), "r"(a3), "r"(b0), "r"(b1));
}
__device__ __forceinline__ void cp16(void* dst, const void* src) {
    unsigned d = (unsigned)__cvta_generic_to_shared(dst);
    asm volatile("cp.async.cg.shared.global [%0], [%1], 16;"
                 :: "r"(d), "l"(src));
}
#define CP_COMMIT() asm volatile("cp.async.commit_group;")
#define CP_WAIT0()  asm volatile("cp.async.wait_group 0;")

// ---------- tensor-core GEMM (frozen r14 config) ----------
#define A_STRIDE 132
#define W_STRIDE 72
#define KCH 64
#define TG_SMEM_BYTES ((128 * A_STRIDE + 2 * KCH * W_STRIDE) * 4)

template <int N, int ACT, int ACVT>
__device__ __forceinline__ void gemm_tc_body(
    const float* __restrict__ A, const float* __restrict__ W,
    const float* __restrict__ bias, float* __restrict__ C, int M)
{
    extern __shared__ __align__(16) unsigned smem_u[];
    unsigned* A_sh = smem_u;                  // [128][A_STRIDE]
    unsigned* W_b0 = smem_u + 128 * A_STRIDE; // [KCH][W_STRIDE]
    unsigned* W_b1 = W_b0 + KCH * W_STRIDE;

    const int t = threadIdx.x;
    const int w = t >> 5;
    const int lane = t & 31;
    const int mw = w & 3;
    const int nw = w >> 2;
    const int lr = lane >> 2;
    const int lc = lane & 3;
    const int m0 = blockIdx.x * 128;

    if (ACVT) {
        for (int lin = t; lin < 128 * 32; lin += 256) {
            int m = lin >> 5, j = lin & 31;
            uint4 out;
            if (m0 + m < M) {
                float4 vsrc = *(const float4*)(A + (size_t)(m0 + m) * 128 + j * 4);
                out.x = tf32_of(vsrc.x);
                out.y = tf32_of(vsrc.y);
                out.z = tf32_of(vsrc.z);
                out.w = tf32_of(vsrc.w);
            } else {
                out = make_uint4(0u, 0u, 0u, 0u);
            }
            *(uint4*)(A_sh + m * A_STRIDE + j * 4) = out;
        }
    } else {
        for (int lin = t; lin < 128 * 32; lin += 256) {
            int m = lin >> 5, j = lin & 31;
            int mg = m0 + m;
            int mc = (mg < M) ? mg : (M - 1);
            cp16(A_sh + m * A_STRIDE + j * 4, A + (size_t)mc * 128 + j * 4);
        }
    }

    for (int n0 = 0; n0 < N; n0 += 64) {
        __syncthreads();
        for (int lin = t; lin < KCH * 16; lin += 256) {
            int kk = lin >> 4, j = lin & 15;
            cp16(W_b0 + kk * W_STRIDE + j * 4, W + (size_t)kk * N + n0 + j * 4);
        }
        CP_COMMIT();

        float acc[2][4][4];
        #pragma unroll
        for (int i = 0; i < 2; i++)
            #pragma unroll
            for (int j = 0; j < 4; j++)
                #pragma unroll
                for (int x = 0; x < 4; x++) acc[i][j][x] = 0.f;

        #pragma unroll
        for (int kc = 0; kc < 2; kc++) {
            CP_WAIT0();
            __syncthreads();

            if (kc < 1) {
                for (int lin = t; lin < KCH * 16; lin += 256) {
                    int kk = lin >> 4, j = lin & 15;
                    cp16(W_b1 + kk * W_STRIDE + j * 4,
                         W + (size_t)(KCH + kk) * N + n0 + j * 4);
                }
                CP_COMMIT();
            }

            unsigned* Wcur = kc ? W_b1 : W_b0;
            #pragma unroll
            for (int k8 = 0; k8 < KCH / 8; k8++) {
                const int kl = k8 * 8;
                const int kg = kc * KCH + kl;
                unsigned a[2][4];
                #pragma unroll
                for (int i = 0; i < 2; i++) {
                    const int r = mw * 32 + i * 16 + lr;
                    a[i][0] = A_sh[r * A_STRIDE + kg + lc];
                    a[i][1] = A_sh[(r + 8) * A_STRIDE + kg + lc];
                    a[i][2] = A_sh[r * A_STRIDE + kg + lc + 4];
                    a[i][3] = A_sh[(r + 8) * A_STRIDE + kg + lc + 4];
                }
                #pragma unroll
                for (int j = 0; j < 4; j++) {
                    const int n = nw * 32 + j * 8 + lr;
                    unsigned b0 = Wcur[(kl + lc) * W_STRIDE + n];
                    unsigned b1 = Wcur[(kl + lc + 4) * W_STRIDE + n];
                    mma_tf32(acc[0][j], a[0][0], a[0][1], a[0][2], a[0][3], b0, b1);
                    mma_tf32(acc[1][j], a[1][0], a[1][1], a[1][2], a[1][3], b0, b1);
                }
            }
        }

        #pragma unroll
        for (int i = 0; i < 2; i++) {
            const int r1 = m0 + mw * 32 + i * 16 + lr;
            const int r2 = r1 + 8;
            #pragma unroll
            for (int j = 0; j < 4; j++) {
                const int cb = n0 + nw * 32 + j * 8 + lc * 2;
                const float b0f = bias[cb], b1f = bias[cb + 1];
                float x0 = acc[i][j][0] + b0f;
                float x1 = acc[i][j][1] + b1f;
                float x2 = acc[i][j][2] + b0f;
                float x3 = acc[i][j][3] + b1f;
                if (ACT) {
                    x0 = __uint_as_float(tf32_of(x0 / (1.0f + __expf(-x0))));
                    x1 = __uint_as_float(tf32_of(x1 / (1.0f + __expf(-x1))));
                    x2 = __uint_as_float(tf32_of(x2 / (1.0f + __expf(-x2))));
                    x3 = __uint_as_float(tf32_of(x3 / (1.0f + __expf(-x3))));
                }
                if (r1 < M) *(float2*)(C + (size_t)r1 * N + cb) = make_float2(x0, x1);
                if (r2 < M) *(float2*)(C + (size_t)r2 * N + cb) = make_float2(x2, x3);
            }
        }
    }
}

__global__ __launch_bounds__(256) void gemm1_kernel(
    const float* __restrict__ A, const float* __restrict__ W,
    const float* __restrict__ bias, int M)
{
    gemm_tc_body<128, 1, 1>(A, W, bias, g_h, M);
}

__global__ __launch_bounds__(256) void gemm2_kernel(
    const float* __restrict__ W, const float* __restrict__ bias, int M)
{
    gemm_tc_body<384, 0, 0>(g_h, W, bias, g_spass, M);
}

// ---------- counting sort of edges by dst ----------
__global__ __launch_bounds__(256) void hist_kernel(const int* __restrict__ edges,
                                                   int n_edges)
{
    int e = blockIdx.x * 256 + threadIdx.x;
    if (e < n_edges) atomicAdd(&g_hist[edges[2 * e + 1]], 1);
}

__global__ __launch_bounds__(1024) void scan_kernel()
{
    __shared__ int warp_sums[32];
    __shared__ int running_sh;
    const int t = threadIdx.x;
    const int lane = t & 31, wid = t >> 5;
    if (t == 0) running_sh = 0;
    __syncthreads();

    for (int base = 0; base < N_NODES; base += 1024) {
        int i = base + t;
        int v = (i < N_NODES) ? g_hist[i] : 0;
        int x = v;
        #pragma unroll
        for (int d = 1; d < 32; d <<= 1) {
            int y = __shfl_up_sync(~0u, x, d);
            if (lane >= d) x += y;
        }
        if (lane == 31) warp_sums[wid] = x;
        __syncthreads();
        if (wid == 0) {
            int s2 = warp_sums[lane];
            #pragma unroll
            for (int d = 1; d < 32; d <<= 1) {
                int y = __shfl_up_sync(~0u, s2, d);
                if (lane >= d) s2 += y;
            }
            warp_sums[lane] = s2;
        }
        __syncthreads();
        int incl = x + (wid > 0 ? warp_sums[wid - 1] : 0) + running_sh;
        if (i < N_NODES) g_hist[i] = incl - v;
        __syncthreads();
        if (t == 1023) running_sh = incl;
        __syncthreads();
    }
}

__global__ __launch_bounds__(256) void scatter_kernel(const int* __restrict__ edges,
                                                      int n_edges)
{
    int e = blockIdx.x * 256 + threadIdx.x;
    if (e < n_edges) {
        int2 sd = ((const int2*)edges)[e];
        int pos = atomicAdd(&g_hist[sd.y], 1);
        g_sorted_sd[pos] = sd;
        g_sorted_idx[pos] = e;
    }
}

// ---------- Edge kernel: dst-sorted, run-cached gathers + run-boundary prefetch ----------
__global__ __launch_bounds__(128) void edge_kernel(
    const float* __restrict__ r_ij,        // [E]
    const float* __restrict__ rnorm,       // [E][3]
    const float* __restrict__ Wr,          // [20][384]
    const float* __restrict__ br,          // [384]
    const float* __restrict__ v_in,        // [N][3][128]
    float* __restrict__ s_out,             // [N][128]
    float* __restrict__ v_out,             // [N][3][128]
    int n_edges)
{
    __shared__ __align__(16) float rb_sh[128][24];  // 20 rbf, fc, rn0..rn2
    __shared__ int src_sh[128];
    __shared__ int dst_sh[128];

    const int t = threadIdx.x;
    const int base = blockIdx.x * 128;

    unsigned long long wrP0[10], wrP1[10], wrP2[10];
    #pragma unroll
    for (int p = 0; p < 10; p++) {
        wrP0[p] = packf(Wr[(2 * p) * 384 + t],       Wr[(2 * p + 1) * 384 + t]);
        wrP1[p] = packf(Wr[(2 * p) * 384 + 128 + t], Wr[(2 * p + 1) * 384 + 128 + t]);
        wrP2[p] = packf(Wr[(2 * p) * 384 + 256 + t], Wr[(2 * p + 1) * 384 + 256 + t]);
    }
    const float br0 = br[t], br1 = br[128 + t], br2 = br[256 + t];

    const int e_my = base + t;
    if (e_my < n_edges) {
        int2 sd = g_sorted_sd[e_my];
        int idx = g_sorted_idx[e_my];
        src_sh[t] = sd.x;
        dst_sh[t] = sd.y;
        float r = r_ij[idx];
        float inv_r = 1.0f / r;
        float q = r * 0.2f;
        #pragma unroll
        for (int n = 1; n <= NRBF; n++) {
            rb_sh[t][n - 1] = sinpif((float)n * q) * inv_r;
        }
        float fc = (r <= 5.0f) ? 0.5f * (cospif(q) + 1.0f) : 0.0f;
        rb_sh[t][20] = fc;
        rb_sh[t][21] = rnorm[3 * idx + 0];
        rb_sh[t][22] = rnorm[3 * idx + 1];
        rb_sh[t][23] = rnorm[3 * idx + 2];
    }
    __syncthreads();

    const int cnt = min(128, n_edges - base);

    // gather values for the current dst run
    int dst_cur = dst_sh[0];
    float sp0, sp1, sp2, vv0, vv1, vv2;
    {
        const float* sp = g_spass + (size_t)dst_cur * 384 + t;
        const float* vp = v_in + (size_t)dst_cur * 384 + t;
        sp0 = sp[0]; sp1 = sp[128]; sp2 = sp[256];
        vv0 = vp[0]; vv1 = vp[128]; vv2 = vp[256];
    }

    for (int e = 0; e < cnt; e++) {
        const int src = src_sh[e];

        // run-boundary prefetch: issue next run's 6 gathers BEFORE this edge's
        // math, so L2 latency is covered by the 30-FFMA2 dot product below.
        const bool chg = (e + 1 < cnt) && (dst_sh[e + 1] != dst_cur);
        float nsp0, nsp1, nsp2, nvv0, nvv1, nvv2;
        int dst_nxt;
        if (chg) {
            dst_nxt = dst_sh[e + 1];
            const float* spn = g_spass + (size_t)dst_nxt * 384 + t;
            const float* vpn = v_in + (size_t)dst_nxt * 384 + t;
            nsp0 = spn[0]; nsp1 = spn[128]; nsp2 = spn[256];
            nvv0 = vpn[0]; nvv1 = vpn[128]; nvv2 = vpn[256];
        }

        const float* row = rb_sh[e];
        unsigned long long a0 = 0ull, a1 = 0ull, a2 = 0ull;
        #pragma unroll
        for (int p = 0; p < 5; p++) {
            ulonglong2 rp = ((const ulonglong2*)row)[p];
            a0 = fma2(rp.x, wrP0[2 * p], a0);
            a0 = fma2(rp.y, wrP0[2 * p + 1], a0);
            a1 = fma2(rp.x, wrP1[2 * p], a1);
            a1 = fma2(rp.y, wrP1[2 * p + 1], a1);
            a2 = fma2(rp.x, wrP2[2 * p], a2);
            a2 = fma2(rp.y, wrP2[2 * p + 1], a2);
        }
        const float fc  = row[20];
        const float rn0 = row[21], rn1 = row[22], rn2 = row[23];

        float g   = (lof(a0) + hif(a0) + br0) * fc * sp0;
        float ds  = (lof(a1) + hif(a1) + br1) * fc * sp1;
        float rep = (lof(a2) + hif(a2) + br2) * fc * sp2;

        atomicAdd(s_out + (size_t)src * 128 + t, ds);

        float* vo = v_out + (size_t)src * 384 + t;
        atomicAdd(vo,       fmaf(vv0, g, rn0 * rep));
        atomicAdd(vo + 128, fmaf(vv1, g, rn1 * rep));
        atomicAdd(vo + 256, fmaf(vv2, g, rn2 * rep));

        if (chg) {
            dst_cur = dst_nxt;
            sp0 = nsp0; sp1 = nsp1; sp2 = nsp2;
            vv0 = nvv0; vv1 = nvv1; vv2 = nvv2;
        }
    }
}

// ---------- launch ----------
extern "C" void kernel_launch(void* const* d_in, const int* in_sizes, int n_in,
                              void* d_out, int out_size)
{
    const float* s     = (const float*)d_in[0];
    const float* v     = (const float*)d_in[1];
    const int*   edges = (const int*)d_in[2];
    const float* r_ij  = (const float*)d_in[3];
    const float* rnorm = (const float*)d_in[4];
    const float* W1    = (const float*)d_in[5];
    const float* b1    = (const float*)d_in[6];
    const float* W2    = (const float*)d_in[7];
    const float* b2    = (const float*)d_in[8];
    const float* Wr    = (const float*)d_in[9];
    const float* br    = (const float*)d_in[10];

    const int n_nodes = in_sizes[0] / EMB;
    const int n_edges = in_sizes[2] / 2;

    float* s_out = (float*)d_out;
    float* v_out = s_out + (size_t)n_nodes * EMB;

    static cudaStream_t s2 = nullptr;
    static cudaEvent_t ev_fork = nullptr, ev_join = nullptr;
    static int* hist_ptr = nullptr;
    if (!s2) {
        cudaStreamCreateWithFlags(&s2, cudaStreamNonBlocking);
        cudaEventCreateWithFlags(&ev_fork, cudaEventDisableTiming);
        cudaEventCreateWithFlags(&ev_join, cudaEventDisableTiming);
        cudaFuncSetAttribute(gemm1_kernel,
            cudaFuncAttributeMaxDynamicSharedMemorySize, TG_SMEM_BYTES);
        cudaFuncSetAttribute(gemm2_kernel,
            cudaFuncAttributeMaxDynamicSharedMemorySize, TG_SMEM_BYTES);
        cudaGetSymbolAddress((void**)&hist_ptr, g_hist);
    }

    // fork: side stream does output-init copies + edge sort, overlapped with GEMMs
    cudaEventRecord(ev_fork, 0);
    cudaStreamWaitEvent(s2, ev_fork, 0);
    cudaMemcpyAsync(s_out, s, (size_t)n_nodes * EMB * sizeof(float),
                    cudaMemcpyDeviceToDevice, s2);
    cudaMemcpyAsync(v_out, v, (size_t)n_nodes * 3 * EMB * sizeof(float),
                    cudaMemcpyDeviceToDevice, s2);
    cudaMemsetAsync(hist_ptr, 0, N_NODES * sizeof(int), s2);
    hist_kernel<<<(n_edges + 255) / 256, 256, 0, s2>>>(edges, n_edges);
    scan_kernel<<<1, 1024, 0, s2>>>();
    scatter_kernel<<<(n_edges + 255) / 256, 256, 0, s2>>>(edges, n_edges);
    cudaEventRecord(ev_join, s2);

    const int tc_grid = (n_nodes + 127) / 128;
    gemm1_kernel<<<tc_grid, 256, TG_SMEM_BYTES>>>(s, W1, b1, n_nodes);
    gemm2_kernel<<<tc_grid, 256, TG_SMEM_BYTES>>>(W2, b2, n_nodes);

    // join: edge kernel needs sorted edges + initialized outputs + g_spass
    cudaStreamWaitEvent(0, ev_join, 0);
    edge_kernel<<<(n_edges + 127) / 128, 128>>>(r_ij, rnorm, Wr, br,
                                                v, s_out, v_out, n_edges);
}

// round 16
// speedup vs baseline: 1.0792x; 1.0792x over previous
#include <cuda_runtime.h>
#include <cstdint>

#define N_NODES 50000
#define MAX_EDGES 800000
#define EMB 128
#define NRBF 20

// Scratch (static device arrays are allowed; runtime alloc is not)
__device__ float g_spass[(size_t)N_NODES * 3 * EMB]; // h@W2+b2
__device__ int   g_hist[N_NODES];                    // histogram -> offsets (cursor)
__device__ int2  g_sorted_sd[MAX_EDGES];             // (src, dst) sorted by dst
__device__ int   g_sorted_idx[MAX_EDGES];            // original edge index

// ---------- f32x2 helpers (edge kernel) ----------
__device__ __forceinline__ unsigned long long fma2(unsigned long long a,
                                                   unsigned long long b,
                                                   unsigned long long c) {
    unsigned long long d;
    asm("fma.rn.f32x2 %0, %1, %2, %3;" : "=l"(d) : "l"(a), "l"(b), "l"(c));
    return d;
}
__device__ __forceinline__ unsigned long long packf(float lo, float hi) {
    unsigned long long r;
    asm("mov.b64 %0, {%1, %2};" : "=l"(r) : "f"(lo), "f"(hi));
    return r;
}
__device__ __forceinline__ float lof(unsigned long long v) {
    return __uint_as_float((unsigned)(v & 0xffffffffull));
}
__device__ __forceinline__ float hif(unsigned long long v) {
    return __uint_as_float((unsigned)(v >> 32));
}

// ---------- mma / cp.async helpers ----------
__device__ __forceinline__ unsigned tf32_of(float f) {
    unsigned r;
    asm("cvt.rna.tf32.f32 %0, %1;" : "=r"(r) : "f"(f));
    return r;
}
__device__ __forceinline__ void mma_tf32(float c[4],
                                         unsigned a0, unsigned a1,
                                         unsigned a2, unsigned a3,
                                         unsigned b0, unsigned b1) {
    asm("mma.sync.aligned.m16n8k8.row.col.f32.tf32.tf32.f32 "
        "{%0,%1,%2,%3}, {%4,%5,%6,%7}, {%8,%9}, {%0,%1,%2,%3};"
        : "+f"(c[0]), "+f"(c[1]), "+f"(c[2]), "+f"(c[3])
        : "r"(a0), "r"(a1), "r"(a2), "r"(a3), "r"(b0), "r"(b1));
}
__device__ __forceinline__ void cp16(void* dst, const void* src) {
    unsigned d = (unsigned)__cvta_generic_to_shared(dst);
    asm volatile("cp.async.cg.shared.global [%0], [%1], 16;"
                 :: "r"(d), "l"(src));
}
#define CP_COMMIT() asm volatile("cp.async.commit_group;")
#define CP_WAIT0()  asm volatile("cp.async.wait_group 0;")

// ---------- fused node MLP: g_spass = silu(s@W1+b1)@W2+b2 ----------
// 256 threads / 8 warps (4m x 2n), block 128 rows; one 64-col MMA pass at a time.
// h is held in registers across phase 1, then written tf32-rounded into A_sh
// (replacing s) so phase 2 consumes it with zero extra staging / gmem traffic.
#define A_STRIDE 132
#define W_STRIDE 72
#define KCH 64
#define TG_SMEM_BYTES ((128 * A_STRIDE + 2 * KCH * W_STRIDE) * 4)

// one 64-wide MMA pass over K=128 (W double-buffered via cp.async)
template <int N>
__device__ __forceinline__ void mma_pass(
    unsigned* A_sh, unsigned* W_b0, unsigned* W_b1,
    const float* __restrict__ W, int n0,
    int t, int mw, int nw, int lr, int lc,
    float acc[2][4][4])
{
    __syncthreads();  // prev pass's W-buffer reads (and A_sh writes) complete
    for (int lin = t; lin < KCH * 16; lin += 256) {
        int kk = lin >> 4, j = lin & 15;
        cp16(W_b0 + kk * W_STRIDE + j * 4, W + (size_t)kk * N + n0 + j * 4);
    }
    CP_COMMIT();

    #pragma unroll
    for (int kc = 0; kc < 2; kc++) {
        CP_WAIT0();
        __syncthreads();

        if (kc < 1) {
            for (int lin = t; lin < KCH * 16; lin += 256) {
                int kk = lin >> 4, j = lin & 15;
                cp16(W_b1 + kk * W_STRIDE + j * 4,
                     W + (size_t)(KCH + kk) * N + n0 + j * 4);
            }
            CP_COMMIT();
        }

        unsigned* Wcur = kc ? W_b1 : W_b0;
        #pragma unroll
        for (int k8 = 0; k8 < KCH / 8; k8++) {
            const int kl = k8 * 8;
            const int kg = kc * KCH + kl;
            unsigned a[2][4];
            #pragma unroll
            for (int i = 0; i < 2; i++) {
                const int r = mw * 32 + i * 16 + lr;
                a[i][0] = A_sh[r * A_STRIDE + kg + lc];
                a[i][1] = A_sh[(r + 8) * A_STRIDE + kg + lc];
                a[i][2] = A_sh[r * A_STRIDE + kg + lc + 4];
                a[i][3] = A_sh[(r + 8) * A_STRIDE + kg + lc + 4];
            }
            #pragma unroll
            for (int j = 0; j < 4; j++) {
                const int n = nw * 32 + j * 8 + lr;
                unsigned b0 = Wcur[(kl + lc) * W_STRIDE + n];
                unsigned b1 = Wcur[(kl + lc + 4) * W_STRIDE + n];
                mma_tf32(acc[0][j], a[0][0], a[0][1], a[0][2], a[0][3], b0, b1);
                mma_tf32(acc[1][j], a[1][0], a[1][1], a[1][2], a[1][3], b0, b1);
            }
        }
    }
}

__global__ __launch_bounds__(256) void fused_mlp_kernel(
    const float* __restrict__ A,  // s [M x 128]
    const float* __restrict__ W1, const float* __restrict__ b1,
    const float* __restrict__ W2, const float* __restrict__ b2,
    int M)
{
    extern __shared__ __align__(16) unsigned smem_u[];
    unsigned* A_sh = smem_u;                  // [128][A_STRIDE]
    unsigned* W_b0 = smem_u + 128 * A_STRIDE; // [KCH][W_STRIDE]
    unsigned* W_b1 = W_b0 + KCH * W_STRIDE;

    const int t = threadIdx.x;
    const int w = t >> 5;
    const int lane = t & 31;
    const int mw = w & 3;
    const int nw = w >> 2;
    const int lr = lane >> 2;
    const int lc = lane & 3;
    const int m0 = blockIdx.x * 128;

    // ---- stage s tile (128 x 128), vectorized RNA rounding
    for (int lin = t; lin < 128 * 32; lin += 256) {
        int m = lin >> 5, j = lin & 31;
        uint4 out;
        if (m0 + m < M) {
            float4 vsrc = *(const float4*)(A + (size_t)(m0 + m) * 128 + j * 4);
            out.x = tf32_of(vsrc.x);
            out.y = tf32_of(vsrc.y);
            out.z = tf32_of(vsrc.z);
            out.w = tf32_of(vsrc.w);
        } else {
            out = make_uint4(0u, 0u, 0u, 0u);
        }
        *(uint4*)(A_sh + m * A_STRIDE + j * 4) = out;
    }

    // ---- phase 1: h = silu(s@W1+b1); both 64-col passes held in registers
    float accH[2][2][4][4];
    #pragma unroll
    for (int p = 0; p < 2; p++)
        #pragma unroll
        for (int i = 0; i < 2; i++)
            #pragma unroll
            for (int j = 0; j < 4; j++)
                #pragma unroll
                for (int x = 0; x < 4; x++) accH[p][i][j][x] = 0.f;

    mma_pass<128>(A_sh, W_b0, W_b1, W1, 0,   t, mw, nw, lr, lc, accH[0]);
    mma_pass<128>(A_sh, W_b0, W_b1, W1, 64,  t, mw, nw, lr, lc, accH[1]);

    __syncthreads();  // all A_sh (s) reads complete before overwrite with h

    // ---- phase-1 epilogue: silu+bias, tf32-round, write h into A_sh
    #pragma unroll
    for (int p = 0; p < 2; p++) {
        #pragma unroll
        for (int i = 0; i < 2; i++) {
            const int r1 = mw * 32 + i * 16 + lr;
            const int r2 = r1 + 8;
            #pragma unroll
            for (int j = 0; j < 4; j++) {
                const int cb = p * 64 + nw * 32 + j * 8 + lc * 2;
                const float b0f = b1[cb], b1f = b1[cb + 1];
                float x0 = accH[p][i][j][0] + b0f;
                float x1 = accH[p][i][j][1] + b1f;
                float x2 = accH[p][i][j][2] + b0f;
                float x3 = accH[p][i][j][3] + b1f;
                x0 = x0 / (1.0f + __expf(-x0));
                x1 = x1 / (1.0f + __expf(-x1));
                x2 = x2 / (1.0f + __expf(-x2));
                x3 = x3 / (1.0f + __expf(-x3));
                A_sh[r1 * A_STRIDE + cb]     = tf32_of(x0);
                A_sh[r1 * A_STRIDE + cb + 1] = tf32_of(x1);
                A_sh[r2 * A_STRIDE + cb]     = tf32_of(x2);
                A_sh[r2 * A_STRIDE + cb + 1] = tf32_of(x3);
            }
        }
    }
    // (mma_pass entry __syncthreads orders these writes before phase-2 reads)

    // ---- phase 2: spass = h@W2+b2 -> g_spass
    for (int n0 = 0; n0 < 384; n0 += 64) {
        float acc[2][4][4];
        #pragma unroll
        for (int i = 0; i < 2; i++)
            #pragma unroll
            for (int j = 0; j < 4; j++)
                #pragma unroll
                for (int x = 0; x < 4; x++) acc[i][j][x] = 0.f;

        mma_pass<384>(A_sh, W_b0, W_b1, W2, n0, t, mw, nw, lr, lc, acc);

        #pragma unroll
        for (int i = 0; i < 2; i++) {
            const int r1 = m0 + mw * 32 + i * 16 + lr;
            const int r2 = r1 + 8;
            #pragma unroll
            for (int j = 0; j < 4; j++) {
                const int cb = n0 + nw * 32 + j * 8 + lc * 2;
                const float b0f = b2[cb], b1f = b2[cb + 1];
                float x0 = acc[i][j][0] + b0f;
                float x1 = acc[i][j][1] + b1f;
                float x2 = acc[i][j][2] + b0f;
                float x3 = acc[i][j][3] + b1f;
                if (r1 < M) *(float2*)(g_spass + (size_t)r1 * 384 + cb) = make_float2(x0, x1);
                if (r2 < M) *(float2*)(g_spass + (size_t)r2 * 384 + cb) = make_float2(x2, x3);
            }
        }
    }
}

// ---------- counting sort of edges by dst ----------
__global__ __launch_bounds__(256) void hist_kernel(const int* __restrict__ edges,
                                                   int n_edges)
{
    int e = blockIdx.x * 256 + threadIdx.x;
    if (e < n_edges) atomicAdd(&g_hist[edges[2 * e + 1]], 1);
}

__global__ __launch_bounds__(1024) void scan_kernel()
{
    __shared__ int warp_sums[32];
    __shared__ int running_sh;
    const int t = threadIdx.x;
    const int lane = t & 31, wid = t >> 5;
    if (t == 0) running_sh = 0;
    __syncthreads();

    for (int base = 0; base < N_NODES; base += 1024) {
        int i = base + t;
        int v = (i < N_NODES) ? g_hist[i] : 0;
        int x = v;
        #pragma unroll
        for (int d = 1; d < 32; d <<= 1) {
            int y = __shfl_up_sync(~0u, x, d);
            if (lane >= d) x += y;
        }
        if (lane == 31) warp_sums[wid] = x;
        __syncthreads();
        if (wid == 0) {
            int s2 = warp_sums[lane];
            #pragma unroll
            for (int d = 1; d < 32; d <<= 1) {
                int y = __shfl_up_sync(~0u, s2, d);
                if (lane >= d) s2 += y;
            }
            warp_sums[lane] = s2;
        }
        __syncthreads();
        int incl = x + (wid > 0 ? warp_sums[wid - 1] : 0) + running_sh;
        if (i < N_NODES) g_hist[i] = incl - v;
        __syncthreads();
        if (t == 1023) running_sh = incl;
        __syncthreads();
    }
}

__global__ __launch_bounds__(256) void scatter_kernel(const int* __restrict__ edges,
                                                      int n_edges)
{
    int e = blockIdx.x * 256 + threadIdx.x;
    if (e < n_edges) {
        int2 sd = ((const int2*)edges)[e];
        int pos = atomicAdd(&g_hist[sd.y], 1);
        g_sorted_sd[pos] = sd;
        g_sorted_idx[pos] = e;
    }
}

// ---------- Edge kernel (r12 proven): dst-sorted, register-cached gathers ----------
__global__ __launch_bounds__(128) void edge_kernel(
    const float* __restrict__ r_ij,        // [E]
    const float* __restrict__ rnorm,       // [E][3]
    const float* __restrict__ Wr,          // [20][384]
    const float* __restrict__ br,          // [384]
    const float* __restrict__ v_in,        // [N][3][128]
    float* __restrict__ s_out,             // [N][128]
    float* __restrict__ v_out,             // [N][3][128]
    int n_edges)
{
    __shared__ __align__(16) float rb_sh[128][24];  // 20 rbf, fc, rn0..rn2
    __shared__ int src_sh[128];
    __shared__ int dst_sh[128];

    const int t = threadIdx.x;
    const int base = blockIdx.x * 128;

    unsigned long long wrP0[10], wrP1[10], wrP2[10];
    #pragma unroll
    for (int p = 0; p < 10; p++) {
        wrP0[p] = packf(Wr[(2 * p) * 384 + t],       Wr[(2 * p + 1) * 384 + t]);
        wrP1[p] = packf(Wr[(2 * p) * 384 + 128 + t], Wr[(2 * p + 1) * 384 + 128 + t]);
        wrP2[p] = packf(Wr[(2 * p) * 384 + 256 + t], Wr[(2 * p + 1) * 384 + 256 + t]);
    }
    const float br0 = br[t], br1 = br[128 + t], br2 = br[256 + t];

    const int e_my = base + t;
    if (e_my < n_edges) {
        int2 sd = g_sorted_sd[e_my];
        int idx = g_sorted_idx[e_my];
        src_sh[t] = sd.x;
        dst_sh[t] = sd.y;
        float r = r_ij[idx];
        float inv_r = 1.0f / r;
        float q = r * 0.2f;
        #pragma unroll
        for (int n = 1; n <= NRBF; n++) {
            rb_sh[t][n - 1] = sinpif((float)n * q) * inv_r;
        }
        float fc = (r <= 5.0f) ? 0.5f * (cospif(q) + 1.0f) : 0.0f;
        rb_sh[t][20] = fc;
        rb_sh[t][21] = rnorm[3 * idx + 0];
        rb_sh[t][22] = rnorm[3 * idx + 1];
        rb_sh[t][23] = rnorm[3 * idx + 2];
    }
    __syncthreads();

    const int cnt = min(128, n_edges - base);

    int dst_prev = -1;
    float sp0 = 0.f, sp1 = 0.f, sp2 = 0.f, vv0 = 0.f, vv1 = 0.f, vv2 = 0.f;

    for (int e = 0; e < cnt; e++) {
        const int src = src_sh[e];
        const int dst = dst_sh[e];

        if (dst != dst_prev) {
            const float* sp = g_spass + (size_t)dst * 384 + t;
            const float* vp = v_in + (size_t)dst * 384 + t;
            sp0 = sp[0]; sp1 = sp[128]; sp2 = sp[256];
            vv0 = vp[0]; vv1 = vp[128]; vv2 = vp[256];
            dst_prev = dst;
        }

        const float* row = rb_sh[e];
        unsigned long long a0 = 0ull, a1 = 0ull, a2 = 0ull;
        #pragma unroll
        for (int p = 0; p < 5; p++) {
            ulonglong2 rp = ((const ulonglong2*)row)[p];
            a0 = fma2(rp.x, wrP0[2 * p], a0);
            a0 = fma2(rp.y, wrP0[2 * p + 1], a0);
            a1 = fma2(rp.x, wrP1[2 * p], a1);
            a1 = fma2(rp.y, wrP1[2 * p + 1], a1);
            a2 = fma2(rp.x, wrP2[2 * p], a2);
            a2 = fma2(rp.y, wrP2[2 * p + 1], a2);
        }
        const float fc  = row[20];
        const float rn0 = row[21], rn1 = row[22], rn2 = row[23];

        float g   = (lof(a0) + hif(a0) + br0) * fc * sp0;
        float ds  = (lof(a1) + hif(a1) + br1) * fc * sp1;
        float rep = (lof(a2) + hif(a2) + br2) * fc * sp2;

        atomicAdd(s_out + (size_t)src * 128 + t, ds);

        float* vo = v_out + (size_t)src * 384 + t;
        atomicAdd(vo,       fmaf(vv0, g, rn0 * rep));
        atomicAdd(vo + 128, fmaf(vv1, g, rn1 * rep));
        atomicAdd(vo + 256, fmaf(vv2, g, rn2 * rep));
    }
}

// ---------- launch ----------
extern "C" void kernel_launch(void* const* d_in, const int* in_sizes, int n_in,
                              void* d_out, int out_size)
{
    const float* s     = (const float*)d_in[0];
    const float* v     = (const float*)d_in[1];
    const int*   edges = (const int*)d_in[2];
    const float* r_ij  = (const float*)d_in[3];
    const float* rnorm = (const float*)d_in[4];
    const float* W1    = (const float*)d_in[5];
    const float* b1    = (const float*)d_in[6];
    const float* W2    = (const float*)d_in[7];
    const float* b2    = (const float*)d_in[8];
    const float* Wr    = (const float*)d_in[9];
    const float* br    = (const float*)d_in[10];

    const int n_nodes = in_sizes[0] / EMB;
    const int n_edges = in_sizes[2] / 2;

    float* s_out = (float*)d_out;
    float* v_out = s_out + (size_t)n_nodes * EMB;

    static cudaStream_t s2 = nullptr;
    static cudaEvent_t ev_fork = nullptr, ev_join = nullptr;
    static int* hist_ptr = nullptr;
    if (!s2) {
        cudaStreamCreateWithFlags(&s2, cudaStreamNonBlocking);
        cudaEventCreateWithFlags(&ev_fork, cudaEventDisableTiming);
        cudaEventCreateWithFlags(&ev_join, cudaEventDisableTiming);
        cudaFuncSetAttribute(fused_mlp_kernel,
            cudaFuncAttributeMaxDynamicSharedMemorySize, TG_SMEM_BYTES);
        cudaGetSymbolAddress((void**)&hist_ptr, g_hist);
    }

    // fork: side stream does output-init copies + edge sort, overlapped with MLP
    cudaEventRecord(ev_fork, 0);
    cudaStreamWaitEvent(s2, ev_fork, 0);
    cudaMemcpyAsync(s_out, s, (size_t)n_nodes * EMB * sizeof(float),
                    cudaMemcpyDeviceToDevice, s2);
    cudaMemcpyAsync(v_out, v, (size_t)n_nodes * 3 * EMB * sizeof(float),
                    cudaMemcpyDeviceToDevice, s2);
    cudaMemsetAsync(hist_ptr, 0, N_NODES * sizeof(int), s2);
    hist_kernel<<<(n_edges + 255) / 256, 256, 0, s2>>>(edges, n_edges);
    scan_kernel<<<1, 1024, 0, s2>>>();
    scatter_kernel<<<(n_edges + 255) / 256, 256, 0, s2>>>(edges, n_edges);
    cudaEventRecord(ev_join, s2);

    const int tc_grid = (n_nodes + 127) / 128;
    fused_mlp_kernel<<<tc_grid, 256, TG_SMEM_BYTES>>>(s, W1, b1, W2, b2, n_nodes);

    // join: edge kernel needs sorted edges + initialized outputs + g_spass
    cudaStreamWaitEvent(0, ev_join, 0);
    edge_kernel<<<(n_edges + 127) / 128, 128>>>(r_ij, rnorm, Wr, br,
                                                v, s_out, v_out, n_edges);
}

// round 17
// speedup vs baseline: 1.1068x; 1.0256x over previous
#include <cuda_runtime.h>
#include <cstdint>

#define N_NODES 50000
#define MAX_EDGES 800000
#define EMB 128
#define NRBF 20

// Scratch (static device arrays are allowed; runtime alloc is not)
__device__ float  g_spass[(size_t)N_NODES * 3 * EMB]; // h@W2+b2
__device__ int    g_hist[N_NODES];                    // histogram -> offsets (cursor)
__device__ int2   g_sorted_sd[MAX_EDGES];             // (src, dst) sorted by dst
__device__ float4 g_sorted_geo[MAX_EDGES];            // (r, rn0, rn1, rn2) sorted

// ---------- f32x2 helpers (edge kernel) ----------
__device__ __forceinline__ unsigned long long fma2(unsigned long long a,
                                                   unsigned long long b,
                                                   unsigned long long c) {
    unsigned long long d;
    asm("fma.rn.f32x2 %0, %1, %2, %3;" : "=l"(d) : "l"(a), "l"(b), "l"(c));
    return d;
}
__device__ __forceinline__ unsigned long long packf(float lo, float hi) {
    unsigned long long r;
    asm("mov.b64 %0, {%1, %2};" : "=l"(r) : "f"(lo), "f"(hi));
    return r;
}
__device__ __forceinline__ float lof(unsigned long long v) {
    return __uint_as_float((unsigned)(v & 0xffffffffull));
}
__device__ __forceinline__ float hif(unsigned long long v) {
    return __uint_as_float((unsigned)(v >> 32));
}

// ---------- mma / cp.async helpers ----------
__device__ __forceinline__ unsigned tf32_of(float f) {
    unsigned r;
    asm("cvt.rna.tf32.f32 %0, %1;" : "=r"(r) : "f"(f));
    return r;
}
__device__ __forceinline__ void mma_tf32(float c[4],
                                         unsigned a0, unsigned a1,
                                         unsigned a2, unsigned a3,
                                         unsigned b0, unsigned b1) {
    asm("mma.sync.aligned.m16n8k8.row.col.f32.tf32.tf32.f32 "
        "{%0,%1,%2,%3}, {%4,%5,%6,%7}, {%8,%9}, {%0,%1,%2,%3};"
        : "+f"(c[0]), "+f"(c[1]), "+f"(c[2]), "+f"(c[3])
        : "r"(a0), "r"(a1), "r"(a2), "r"(a3), "r"(b0), "r"(b1));
}
__device__ __forceinline__ void cp16(void* dst, const void* src) {
    unsigned d = (unsigned)__cvta_generic_to_shared(dst);
    asm volatile("cp.async.cg.shared.global [%0], [%1], 16;"
                 :: "r"(d), "l"(src));
}
#define CP_COMMIT() asm volatile("cp.async.commit_group;")
#define CP_WAIT0()  asm volatile("cp.async.wait_group 0;")

// ---------- fused node MLP (frozen r16): g_spass = silu(s@W1+b1)@W2+b2 ----------
#define A_STRIDE 132
#define W_STRIDE 72
#define KCH 64
#define TG_SMEM_BYTES ((128 * A_STRIDE + 2 * KCH * W_STRIDE) * 4)

template <int N>
__device__ __forceinline__ void mma_pass(
    unsigned* A_sh, unsigned* W_b0, unsigned* W_b1,
    const float* __restrict__ W, int n0,
    int t, int mw, int nw, int lr, int lc,
    float acc[2][4][4])
{
    __syncthreads();  // prev pass's W-buffer reads (and A_sh writes) complete
    for (int lin = t; lin < KCH * 16; lin += 256) {
        int kk = lin >> 4, j = lin & 15;
        cp16(W_b0 + kk * W_STRIDE + j * 4, W + (size_t)kk * N + n0 + j * 4);
    }
    CP_COMMIT();

    #pragma unroll
    for (int kc = 0; kc < 2; kc++) {
        CP_WAIT0();
        __syncthreads();

        if (kc < 1) {
            for (int lin = t; lin < KCH * 16; lin += 256) {
                int kk = lin >> 4, j = lin & 15;
                cp16(W_b1 + kk * W_STRIDE + j * 4,
                     W + (size_t)(KCH + kk) * N + n0 + j * 4);
            }
            CP_COMMIT();
        }

        unsigned* Wcur = kc ? W_b1 : W_b0;
        #pragma unroll
        for (int k8 = 0; k8 < KCH / 8; k8++) {
            const int kl = k8 * 8;
            const int kg = kc * KCH + kl;
            unsigned a[2][4];
            #pragma unroll
            for (int i = 0; i < 2; i++) {
                const int r = mw * 32 + i * 16 + lr;
                a[i][0] = A_sh[r * A_STRIDE + kg + lc];
                a[i][1] = A_sh[(r + 8) * A_STRIDE + kg + lc];
                a[i][2] = A_sh[r * A_STRIDE + kg + lc + 4];
                a[i][3] = A_sh[(r + 8) * A_STRIDE + kg + lc + 4];
            }
            #pragma unroll
            for (int j = 0; j < 4; j++) {
                const int n = nw * 32 + j * 8 + lr;
                unsigned b0 = Wcur[(kl + lc) * W_STRIDE + n];
                unsigned b1 = Wcur[(kl + lc + 4) * W_STRIDE + n];
                mma_tf32(acc[0][j], a[0][0], a[0][1], a[0][2], a[0][3], b0, b1);
                mma_tf32(acc[1][j], a[1][0], a[1][1], a[1][2], a[1][3], b0, b1);
            }
        }
    }
}

__global__ __launch_bounds__(256) void fused_mlp_kernel(
    const float* __restrict__ A,  // s [M x 128]
    const float* __restrict__ W1, const float* __restrict__ b1,
    const float* __restrict__ W2, const float* __restrict__ b2,
    int M)
{
    extern __shared__ __align__(16) unsigned smem_u[];
    unsigned* A_sh = smem_u;                  // [128][A_STRIDE]
    unsigned* W_b0 = smem_u + 128 * A_STRIDE; // [KCH][W_STRIDE]
    unsigned* W_b1 = W_b0 + KCH * W_STRIDE;

    const int t = threadIdx.x;
    const int w = t >> 5;
    const int lane = t & 31;
    const int mw = w & 3;
    const int nw = w >> 2;
    const int lr = lane >> 2;
    const int lc = lane & 3;
    const int m0 = blockIdx.x * 128;

    // ---- stage s tile (128 x 128), vectorized RNA rounding
    for (int lin = t; lin < 128 * 32; lin += 256) {
        int m = lin >> 5, j = lin & 31;
        uint4 out;
        if (m0 + m < M) {
            float4 vsrc = *(const float4*)(A + (size_t)(m0 + m) * 128 + j * 4);
            out.x = tf32_of(vsrc.x);
            out.y = tf32_of(vsrc.y);
            out.z = tf32_of(vsrc.z);
            out.w = tf32_of(vsrc.w);
        } else {
            out = make_uint4(0u, 0u, 0u, 0u);
        }
        *(uint4*)(A_sh + m * A_STRIDE + j * 4) = out;
    }

    // ---- phase 1: h = silu(s@W1+b1); both 64-col passes held in registers
    float accH[2][2][4][4];
    #pragma unroll
    for (int p = 0; p < 2; p++)
        #pragma unroll
        for (int i = 0; i < 2; i++)
            #pragma unroll
            for (int j = 0; j < 4; j++)
                #pragma unroll
                for (int x = 0; x < 4; x++) accH[p][i][j][x] = 0.f;

    mma_pass<128>(A_sh, W_b0, W_b1, W1, 0,   t, mw, nw, lr, lc, accH[0]);
    mma_pass<128>(A_sh, W_b0, W_b1, W1, 64,  t, mw, nw, lr, lc, accH[1]);

    __syncthreads();  // all A_sh (s) reads complete before overwrite with h

    // ---- phase-1 epilogue: silu+bias, tf32-round, write h into A_sh
    #pragma unroll
    for (int p = 0; p < 2; p++) {
        #pragma unroll
        for (int i = 0; i < 2; i++) {
            const int r1 = mw * 32 + i * 16 + lr;
            const int r2 = r1 + 8;
            #pragma unroll
            for (int j = 0; j < 4; j++) {
                const int cb = p * 64 + nw * 32 + j * 8 + lc * 2;
                const float b0f = b1[cb], b1f = b1[cb + 1];
                float x0 = accH[p][i][j][0] + b0f;
                float x1 = accH[p][i][j][1] + b1f;
                float x2 = accH[p][i][j][2] + b0f;
                float x3 = accH[p][i][j][3] + b1f;
                x0 = x0 / (1.0f + __expf(-x0));
                x1 = x1 / (1.0f + __expf(-x1));
                x2 = x2 / (1.0f + __expf(-x2));
                x3 = x3 / (1.0f + __expf(-x3));
                A_sh[r1 * A_STRIDE + cb]     = tf32_of(x0);
                A_sh[r1 * A_STRIDE + cb + 1] = tf32_of(x1);
                A_sh[r2 * A_STRIDE + cb]     = tf32_of(x2);
                A_sh[r2 * A_STRIDE + cb + 1] = tf32_of(x3);
            }
        }
    }
    // (mma_pass entry __syncthreads orders these writes before phase-2 reads)

    // ---- phase 2: spass = h@W2+b2 -> g_spass
    for (int n0 = 0; n0 < 384; n0 += 64) {
        float acc[2][4][4];
        #pragma unroll
        for (int i = 0; i < 2; i++)
            #pragma unroll
            for (int j = 0; j < 4; j++)
                #pragma unroll
                for (int x = 0; x < 4; x++) acc[i][j][x] = 0.f;

        mma_pass<384>(A_sh, W_b0, W_b1, W2, n0, t, mw, nw, lr, lc, acc);

        #pragma unroll
        for (int i = 0; i < 2; i++) {
            const int r1 = m0 + mw * 32 + i * 16 + lr;
            const int r2 = r1 + 8;
            #pragma unroll
            for (int j = 0; j < 4; j++) {
                const int cb = n0 + nw * 32 + j * 8 + lc * 2;
                const float b0f = b2[cb], b1f = b2[cb + 1];
                float x0 = acc[i][j][0] + b0f;
                float x1 = acc[i][j][1] + b1f;
                float x2 = acc[i][j][2] + b0f;
                float x3 = acc[i][j][3] + b1f;
                if (r1 < M) *(float2*)(g_spass + (size_t)r1 * 384 + cb) = make_float2(x0, x1);
                if (r2 < M) *(float2*)(g_spass + (size_t)r2 * 384 + cb) = make_float2(x2, x3);
            }
        }
    }
}

// ---------- counting sort of edges by dst ----------
__global__ __launch_bounds__(256) void hist_kernel(const int* __restrict__ edges,
                                                   int n_edges)
{
    int e = blockIdx.x * 256 + threadIdx.x;
    if (e < n_edges) atomicAdd(&g_hist[edges[2 * e + 1]], 1);
}

__global__ __launch_bounds__(1024) void scan_kernel()
{
    __shared__ int warp_sums[32];
    __shared__ int running_sh;
    const int t = threadIdx.x;
    const int lane = t & 31, wid = t >> 5;
    if (t == 0) running_sh = 0;
    __syncthreads();

    for (int base = 0; base < N_NODES; base += 1024) {
        int i = base + t;
        int v = (i < N_NODES) ? g_hist[i] : 0;
        int x = v;
        #pragma unroll
        for (int d = 1; d < 32; d <<= 1) {
            int y = __shfl_up_sync(~0u, x, d);
            if (lane >= d) x += y;
        }
        if (lane == 31) warp_sums[wid] = x;
        __syncthreads();
        if (wid == 0) {
            int s2 = warp_sums[lane];
            #pragma unroll
            for (int d = 1; d < 32; d <<= 1) {
                int y = __shfl_up_sync(~0u, s2, d);
                if (lane >= d) s2 += y;
            }
            warp_sums[lane] = s2;
        }
        __syncthreads();
        int incl = x + (wid > 0 ? warp_sums[wid - 1] : 0) + running_sh;
        if (i < N_NODES) g_hist[i] = incl - v;
        __syncthreads();
        if (t == 1023) running_sh = incl;
        __syncthreads();
    }
}

// scatter now carries the geometry payload: coalesced reads of r_ij/rnorm here
// (original index order) replace the edge kernel's random 4B/12B gathers.
__global__ __launch_bounds__(256) void scatter_kernel(const int* __restrict__ edges,
                                                      const float* __restrict__ r_ij,
                                                      const float* __restrict__ rnorm,
                                                      int n_edges)
{
    int e = blockIdx.x * 256 + threadIdx.x;
    if (e < n_edges) {
        int2 sd = ((const int2*)edges)[e];
        int pos = atomicAdd(&g_hist[sd.y], 1);
        g_sorted_sd[pos] = sd;
        g_sorted_geo[pos] = make_float4(r_ij[e],
                                        rnorm[3 * e + 0],
                                        rnorm[3 * e + 1],
                                        rnorm[3 * e + 2]);
    }
}

// ---------- Edge kernel (r12 structure): dst-sorted, register-cached gathers ----------
__global__ __launch_bounds__(128) void edge_kernel(
    const float* __restrict__ Wr,          // [20][384]
    const float* __restrict__ br,          // [384]
    const float* __restrict__ v_in,        // [N][3][128]
    float* __restrict__ s_out,             // [N][128]
    float* __restrict__ v_out,             // [N][3][128]
    int n_edges)
{
    __shared__ __align__(16) float rb_sh[128][24];  // 20 rbf, fc, rn0..rn2
    __shared__ int src_sh[128];
    __shared__ int dst_sh[128];

    const int t = threadIdx.x;
    const int base = blockIdx.x * 128;

    unsigned long long wrP0[10], wrP1[10], wrP2[10];
    #pragma unroll
    for (int p = 0; p < 10; p++) {
        wrP0[p] = packf(Wr[(2 * p) * 384 + t],       Wr[(2 * p + 1) * 384 + t]);
        wrP1[p] = packf(Wr[(2 * p) * 384 + 128 + t], Wr[(2 * p + 1) * 384 + 128 + t]);
        wrP2[p] = packf(Wr[(2 * p) * 384 + 256 + t], Wr[(2 * p + 1) * 384 + 256 + t]);
    }
    const float br0 = br[t], br1 = br[128 + t], br2 = br[256 + t];

    const int e_my = base + t;
    if (e_my < n_edges) {
        int2 sd = g_sorted_sd[e_my];
        float4 geo = g_sorted_geo[e_my];   // coalesced: r, rn0, rn1, rn2
        src_sh[t] = sd.x;
        dst_sh[t] = sd.y;
        float r = geo.x;
        float inv_r = 1.0f / r;
        float q = r * 0.2f;
        #pragma unroll
        for (int n = 1; n <= NRBF; n++) {
            rb_sh[t][n - 1] = sinpif((float)n * q) * inv_r;
        }
        float fc = (r <= 5.0f) ? 0.5f * (cospif(q) + 1.0f) : 0.0f;
        rb_sh[t][20] = fc;
        rb_sh[t][21] = geo.y;
        rb_sh[t][22] = geo.z;
        rb_sh[t][23] = geo.w;
    }
    __syncthreads();

    const int cnt = min(128, n_edges - base);

    int dst_prev = -1;
    float sp0 = 0.f, sp1 = 0.f, sp2 = 0.f, vv0 = 0.f, vv1 = 0.f, vv2 = 0.f;

    for (int e = 0; e < cnt; e++) {
        const int src = src_sh[e];
        const int dst = dst_sh[e];

        if (dst != dst_prev) {
            const float* sp = g_spass + (size_t)dst * 384 + t;
            const float* vp = v_in + (size_t)dst * 384 + t;
            sp0 = sp[0]; sp1 = sp[128]; sp2 = sp[256];
            vv0 = vp[0]; vv1 = vp[128]; vv2 = vp[256];
            dst_prev = dst;
        }

        const float* row = rb_sh[e];
        unsigned long long a0 = 0ull, a1 = 0ull, a2 = 0ull;
        #pragma unroll
        for (int p = 0; p < 5; p++) {
            ulonglong2 rp = ((const ulonglong2*)row)[p];
            a0 = fma2(rp.x, wrP0[2 * p], a0);
            a0 = fma2(rp.y, wrP0[2 * p + 1], a0);
            a1 = fma2(rp.x, wrP1[2 * p], a1);
            a1 = fma2(rp.y, wrP1[2 * p + 1], a1);
            a2 = fma2(rp.x, wrP2[2 * p], a2);
            a2 = fma2(rp.y, wrP2[2 * p + 1], a2);
        }
        const float fc  = row[20];
        const float rn0 = row[21], rn1 = row[22], rn2 = row[23];

        float g   = (lof(a0) + hif(a0) + br0) * fc * sp0;
        float ds  = (lof(a1) + hif(a1) + br1) * fc * sp1;
        float rep = (lof(a2) + hif(a2) + br2) * fc * sp2;

        atomicAdd(s_out + (size_t)src * 128 + t, ds);

        float* vo = v_out + (size_t)src * 384 + t;
        atomicAdd(vo,       fmaf(vv0, g, rn0 * rep));
        atomicAdd(vo + 128, fmaf(vv1, g, rn1 * rep));
        atomicAdd(vo + 256, fmaf(vv2, g, rn2 * rep));
    }
}

// ---------- launch ----------
extern "C" void kernel_launch(void* const* d_in, const int* in_sizes, int n_in,
                              void* d_out, int out_size)
{
    const float* s     = (const float*)d_in[0];
    const float* v     = (const float*)d_in[1];
    const int*   edges = (const int*)d_in[2];
    const float* r_ij  = (const float*)d_in[3];
    const float* rnorm = (const float*)d_in[4];
    const float* W1    = (const float*)d_in[5];
    const float* b1    = (const float*)d_in[6];
    const float* W2    = (const float*)d_in[7];
    const float* b2    = (const float*)d_in[8];
    const float* Wr    = (const float*)d_in[9];
    const float* br    = (const float*)d_in[10];

    const int n_nodes = in_sizes[0] / EMB;
    const int n_edges = in_sizes[2] / 2;

    float* s_out = (float*)d_out;
    float* v_out = s_out + (size_t)n_nodes * EMB;

    static cudaStream_t s2 = nullptr, s3 = nullptr;
    static cudaEvent_t ev_fork = nullptr, ev_sort = nullptr, ev_copy = nullptr;
    static int* hist_ptr = nullptr;
    if (!s2) {
        cudaStreamCreateWithFlags(&s2, cudaStreamNonBlocking);
        cudaStreamCreateWithFlags(&s3, cudaStreamNonBlocking);
        cudaEventCreateWithFlags(&ev_fork, cudaEventDisableTiming);
        cudaEventCreateWithFlags(&ev_sort, cudaEventDisableTiming);
        cudaEventCreateWithFlags(&ev_copy, cudaEventDisableTiming);
        cudaFuncSetAttribute(fused_mlp_kernel,
            cudaFuncAttributeMaxDynamicSharedMemorySize, TG_SMEM_BYTES);
        cudaGetSymbolAddress((void**)&hist_ptr, g_hist);
    }

    // fork: sort chain on s2, output-init copies on s3 (parallel), MLP on main
    cudaEventRecord(ev_fork, 0);
    cudaStreamWaitEvent(s2, ev_fork, 0);
    cudaStreamWaitEvent(s3, ev_fork, 0);

    cudaMemsetAsync(hist_ptr, 0, N_NODES * sizeof(int), s2);
    hist_kernel<<<(n_edges + 255) / 256, 256, 0, s2>>>(edges, n_edges);
    scan_kernel<<<1, 1024, 0, s2>>>();
    scatter_kernel<<<(n_edges + 255) / 256, 256, 0, s2>>>(edges, r_ij, rnorm, n_edges);
    cudaEventRecord(ev_sort, s2);

    cudaMemcpyAsync(s_out, s, (size_t)n_nodes * EMB * sizeof(float),
                    cudaMemcpyDeviceToDevice, s3);
    cudaMemcpyAsync(v_out, v, (size_t)n_nodes * 3 * EMB * sizeof(float),
                    cudaMemcpyDeviceToDevice, s3);
    cudaEventRecord(ev_copy, s3);

    const int tc_grid = (n_nodes + 127) / 128;
    fused_mlp_kernel<<<tc_grid, 256, TG_SMEM_BYTES>>>(s, W1, b1, W2, b2, n_nodes);

    // join: edge kernel needs sorted edges + initialized outputs + g_spass
    cudaStreamWaitEvent(0, ev_sort, 0);
    cudaStreamWaitEvent(0, ev_copy, 0);
    edge_kernel<<<(n_edges + 127) / 128, 128>>>(Wr, br, v, s_out, v_out, n_edges);
}